// round 4
// baseline (speedup 1.0000x reference)
#include <cuda_runtime.h>

// RiemannCurvatureTensor: out = [ricci(4096x4096 f32, zero except top-left
// 32x32 gather-reduce block), trace scalar].
// Store-bound: 64MB of STG.128. Fused single kernel, one full wave.

#define MAX_DIM 32

__global__ __launch_bounds__(256, 8)
void ricci_kernel(const float* __restrict__ comp,
                  const int* __restrict__ gidx,
                  const float* __restrict__ gsgn,
                  float* __restrict__ out,
                  int out_size)
{
    const int n4 = out_size >> 2;                       // float4 count (4,194,304)
    const int tid = blockIdx.x * blockDim.x + threadIdx.x;
    const int stride = gridDim.x * blockDim.x;
    float4* __restrict__ out4 = (float4*)out;
    const float4 z = make_float4(0.f, 0.f, 0.f, 0.f);

    const int CORNER_ROWS_V4 = MAX_DIM << 10;           // rows 0..31 in v-space
    const int CORNER_COLS_V4 = MAX_DIM / 4;             // first 8 float4s per row

    for (int v = tid; v < n4; v += stride) {
        // float4 v covers elements [4v,4v+3]; row = v>>10, col4 = v&1023.
        if (v < CORNER_ROWS_V4 && (v & 1023) < CORNER_COLS_V4) {
            const int i = v >> 10;
            const int col = (v & 1023) * 4;
            float vals[4];
            #pragma unroll
            for (int c = 0; c < 4; ++c) {
                const int j = col + c;
                float acc = 0.f;
                #pragma unroll
                for (int k = 0; k < MAX_DIM; ++k) {
                    const int t = k * (MAX_DIM * MAX_DIM) + i * MAX_DIM + j;
                    acc = fmaf(gsgn[t], comp[gidx[t]], acc);
                }
                vals[c] = acc;
            }
            out4[v] = make_float4(vals[0], vals[1], vals[2], vals[3]);
        } else {
            out4[v] = z;
        }
    }

    // Trailing scalar (trace of the 32x32 block; rest of diagonal is zero).
    if ((out_size & 3) != 0 && blockIdx.x == 0 && threadIdx.x < 32) {
        const int i = threadIdx.x;   // lane i computes block[i][i]
        float acc = 0.f;
        #pragma unroll
        for (int k = 0; k < MAX_DIM; ++k) {
            const int t = k * (MAX_DIM * MAX_DIM) + i * MAX_DIM + i;
            acc = fmaf(gsgn[t], comp[gidx[t]], acc);
        }
        #pragma unroll
        for (int off = 16; off > 0; off >>= 1)
            acc += __shfl_xor_sync(0xffffffffu, acc, off);
        if (threadIdx.x == 0)
            out[n4 << 2] = acc;
    }
}

extern "C" void kernel_launch(void* const* d_in, const int* in_sizes, int n_in,
                              void* d_out, int out_size)
{
    const float* comp = (const float*)d_in[0];   // components [10000] f32
    const int*   gidx = (const int*)d_in[1];     // gather_idx [32,32,32] i32
    const float* gsgn = (const float*)d_in[2];   // gather_sign [32,32,32] f32
    float* out = (float*)d_out;

    // One full-occupancy wave on GB300: 152 SMs * 8 blocks * 256 threads.
    const int threads = 256;
    const int blocks  = 152 * 8;
    ricci_kernel<<<blocks, threads>>>(comp, gidx, gsgn, out, out_size);
}